// round 7
// baseline (speedup 1.0000x reference)
#include <cuda_runtime.h>
#include <cuda_bf16.h>
#include <math.h>
#include <stdint.h>

#define NB 1024
#define ND 64
#define NH 512

// ---------------- scratch ----------------------------------------------------
__device__ __align__(256) float g_A  [NH*NH];   // A[k,l] = W2[k,l]*C[l,k]
__device__ __align__(256) float g_AT [NH*NH];
__device__ __align__(256) float g_W2T[NH*NH];
__device__ __align__(256) float g_W3T[ND*NH];
__device__ __align__(256) float g_W1T[NH*ND];
__device__ __align__(256) float g_w3s[NH];
__device__ __align__(256) float g_h1 [NB*NH];
__device__ __align__(256) float g_h2 [NB*NH];
__device__ __align__(256) float g_U  [NB*NH];
__device__ __align__(256) float g_V  [NB*NH];
__device__ __align__(256) float g_wb [NB*NH];
__device__ __align__(256) float g_r1 [NB*NH];   // h2raw, later qw_raw
__device__ __align__(256) float g_r2 [NB*NH];   // z2
__device__ __align__(256) float g_s  [NB*ND];
__device__ __align__(256) float g_y  [NB*ND];
__device__ __align__(256) float g_st [NB];

// ---------------- helpers ------------------------------------------------
__device__ __forceinline__ uint32_t smem_u32(const void* p) {
    return (uint32_t)__cvta_generic_to_shared(p);
}
__device__ __forceinline__ void sts_v2(uint32_t addr, uint32_t a, uint32_t b) {
    asm volatile("st.shared.v2.b32 [%0], {%1,%2};" :: "r"(addr), "r"(a), "r"(b));
}
__device__ __forceinline__ void split2(float x0, float x1, uint32_t& hi, uint32_t& lo) {
    __nv_bfloat16 h0 = __float2bfloat16(x0), h1 = __float2bfloat16(x1);
    __nv_bfloat16 l0 = __float2bfloat16(x0 - __bfloat162float(h0));
    __nv_bfloat16 l1 = __float2bfloat16(x1 - __bfloat162float(h1));
    __nv_bfloat162 H; H.x = h0; H.y = h1;
    __nv_bfloat162 L; L.x = l0; L.y = l1;
    hi = *reinterpret_cast<uint32_t*>(&H);
    lo = *reinterpret_cast<uint32_t*>(&L);
}
__device__ __forceinline__ void ldsm_x4(uint32_t* r, uint32_t addr) {
    asm volatile("ldmatrix.sync.aligned.m8n8.x4.shared.b16 {%0,%1,%2,%3}, [%4];"
                 : "=r"(r[0]), "=r"(r[1]), "=r"(r[2]), "=r"(r[3]) : "r"(addr));
}
__device__ __forceinline__ void ldsm_x2(uint32_t* r, uint32_t addr) {
    asm volatile("ldmatrix.sync.aligned.m8n8.x2.shared.b16 {%0,%1}, [%2];"
                 : "=r"(r[0]), "=r"(r[1]) : "r"(addr));
}
__device__ __forceinline__ void mma16816(float* c, const uint32_t* a, const uint32_t* b) {
    asm volatile(
        "mma.sync.aligned.m16n8k16.row.col.f32.bf16.bf16.f32 "
        "{%0,%1,%2,%3}, {%4,%5,%6,%7}, {%8,%9}, {%0,%1,%2,%3};"
        : "+f"(c[0]), "+f"(c[1]), "+f"(c[2]), "+f"(c[3])
        : "r"(a[0]), "r"(a[1]), "r"(a[2]), "r"(a[3]), "r"(b[0]), "r"(b[1]));
}
__device__ __forceinline__ uint32_t sw128(uint32_t byte) {
    return byte ^ ((byte >> 3) & 0x70);
}

// ---------------- prep -------------------------------------------------------
__global__ void prep_kernel(const float* __restrict__ W1,
                            const float* __restrict__ W2,
                            const float* __restrict__ W3) {
    int k = blockIdx.x * 16 + threadIdx.x;
    int l = blockIdx.y * 16 + threadIdx.y;
    float c = 0.f;
#pragma unroll
    for (int i = 0; i < ND; i++) c += W3[l*ND + i] * W1[i*NH + k];
    float w2 = W2[k*NH + l];
    float a  = w2 * c;
    g_A [k*NH + l] = a;
    g_AT[l*NH + k] = a;
    g_W2T[l*NH + k] = w2;
    if (l < ND) g_W1T[k*ND + l] = W1[l*NH + k];
    if (k < ND) g_W3T[k*NH + l] = W3[l*ND + k];
    if (k == 0 && blockIdx.x == 0) {
        float ssum = 0.f;
#pragma unroll
        for (int j = 0; j < ND; j++) ssum += W3[l*ND + j];
        g_w3s[l] = ssum;
    }
}

// ---------------- split-bf16 warp-MMA GEMM ------------------------------------
enum { TM_L1 = 0, TM_H2 = 1, TM_VU = 2, TM_P = 3, TM_QW = 4 };

template<int TMODE, int KDIM, int LDA, int LDB, int BM>
__global__ void __launch_bounds__(256, 1)
tmma(const float* __restrict__ pX, const float* __restrict__ pB,
     const float* __restrict__ pC, const float* __restrict__ pT,
     const float* __restrict__ w1row) {
    extern __shared__ __align__(1024) char tsm[];
    const uint32_t sb = smem_u32(tsm);
    constexpr int XSZ = BM * 128;          // BM rows x 64 cols x 2B
    constexpr uint32_t OFF_XH = 0, OFF_XL = XSZ;
    constexpr uint32_t OFF_BH = 2 * XSZ, OFF_BL = 2 * XSZ + 8192;
    constexpr int NT = (BM == 128) ? 4 : 2;

    const int tid  = threadIdx.x;
    const int lane = tid & 31, wid = tid >> 5;
    const int zm = blockIdx.z;
    const int n0 = blockIdx.x * 64;
    const int m0 = blockIdx.y * BM;
    const int wm = (BM == 128 ? (wid & 3) : (wid & 1)) * 32;
    const int wn = (BM == 128 ? (wid >> 2) * 32 : (wid >> 1) * 16);

    const float* Xsrc =
        (TMODE == TM_L1) ? pX :
        (TMODE == TM_H2) ? g_h1 :
        (TMODE == TM_VU) ? (zm ? g_h2 : g_h1) :
        (TMODE == TM_P)  ? g_y : g_wb;
    const float* Bsrc =
        (TMODE == TM_L1) ? g_W1T :
        (TMODE == TM_H2) ? g_W2T :
        (TMODE == TM_VU) ? (zm ? g_A : g_AT) : pB;
    float* outp =
        (TMODE == TM_L1) ? g_h1 :
        (TMODE == TM_H2) ? (zm ? g_r2 : g_r1) :
        (TMODE == TM_VU) ? (zm ? g_U : g_V) :
        (TMODE == TM_P)  ? g_wb : g_r1;

    float acc[2][NT][4];
#pragma unroll
    for (int mt = 0; mt < 2; mt++)
#pragma unroll
        for (int nt = 0; nt < NT; nt++)
#pragma unroll
            for (int i = 0; i < 4; i++) acc[mt][nt][i] = 0.f;

    for (int k0 = 0; k0 < KDIM; k0 += 64) {
        // ---- X tile: BM x 64 fp32 -> bf16 hi/lo, SW128 ----
        {
            const int row   = (BM == 128) ? (tid >> 1) : (tid >> 2);
            const int cbase = (BM == 128) ? ((tid & 1) * 32) : ((tid & 3) * 16);
            constexpr int NF4 = (BM == 128) ? 8 : 4;
            const float* xr = Xsrc + (size_t)(m0 + row) * LDA + k0;
#pragma unroll
            for (int i = 0; i < NF4; i++) {
                const int col = cbase + i * 4;
                float4 v = *(const float4*)(xr + col);
                if (TMODE == TM_H2 && zm) {       // d1 = (1-h1^2)*w1t[k]
                    float4 w = *(const float4*)(w1row + k0 + col);
                    v.x = (1.f - v.x*v.x) * w.x; v.y = (1.f - v.y*v.y) * w.y;
                    v.z = (1.f - v.z*v.z) * w.z; v.w = (1.f - v.w*v.w) * w.w;
                } else if (TMODE == TM_VU) {      // a = 1-h^2
                    v.x = 1.f - v.x*v.x; v.y = 1.f - v.y*v.y;
                    v.z = 1.f - v.z*v.z; v.w = 1.f - v.w*v.w;
                }
                uint32_t h01, l01, h23, l23;
                split2(v.x, v.y, h01, l01);
                split2(v.z, v.w, h23, l23);
                uint32_t sw = sw128(row * 128 + col * 2);
                sts_v2(sb + OFF_XH + sw, h01, h23);
                sts_v2(sb + OFF_XL + sw, l01, l23);
            }
        }
        // ---- B tile: 64 x 64 ----
        {
            const int row = tid >> 2;
            const int q   = (tid & 3) * 16;
            const float* br = Bsrc + (size_t)(n0 + row) * LDB + k0;
#pragma unroll
            for (int i = 0; i < 4; i++) {
                const int col = q + i * 4;
                float4 v = *(const float4*)(br + col);
                uint32_t h01, l01, h23, l23;
                split2(v.x, v.y, h01, l01);
                split2(v.z, v.w, h23, l23);
                uint32_t sw = sw128(row * 128 + col * 2);
                sts_v2(sb + OFF_BH + sw, h01, h23);
                sts_v2(sb + OFF_BL + sw, l01, l23);
            }
        }
        __syncthreads();

#pragma unroll
        for (int ks = 0; ks < 4; ks++) {
            uint32_t aH[2][4], aL[2][4];
#pragma unroll
            for (int mt = 0; mt < 2; mt++) {
                uint32_t byte = (uint32_t)(wm + mt * 16 + (lane & 15)) * 128
                              + ks * 32 + (lane >> 4) * 16;
                uint32_t sw = sw128(byte);
                ldsm_x4(aH[mt], sb + OFF_XH + sw);
                ldsm_x4(aL[mt], sb + OFF_XL + sw);
            }
            uint32_t bH[NT][2], bL[NT][2];
#pragma unroll
            for (int nt = 0; nt < NT; nt++) {
                uint32_t byte = (uint32_t)(wn + nt * 8 + (lane & 7)) * 128
                              + ks * 32 + ((lane >> 3) & 1) * 16;
                uint32_t sw = sw128(byte);
                ldsm_x2(bH[nt], sb + OFF_BH + sw);
                ldsm_x2(bL[nt], sb + OFF_BL + sw);
            }
#pragma unroll
            for (int mt = 0; mt < 2; mt++)
#pragma unroll
                for (int nt = 0; nt < NT; nt++) {
                    mma16816(acc[mt][nt], aH[mt], bH[nt]);
                    mma16816(acc[mt][nt], aH[mt], bL[nt]);
                    mma16816(acc[mt][nt], aL[mt], bH[nt]);
                }
        }
        __syncthreads();
    }

    // ---- epilogue ----
#pragma unroll
    for (int mt = 0; mt < 2; mt++)
#pragma unroll
        for (int nt = 0; nt < NT; nt++) {
            const int row = m0 + wm + mt * 16 + (lane >> 2);
            const int col = n0 + wn + nt * 8 + (lane & 3) * 2;
            const float* a = acc[mt][nt];
            size_t i0 = (size_t)row * NH + col;
            size_t i1 = (size_t)(row + 8) * NH + col;
            if constexpr (TMODE == TM_L1) {
                float t0 = pT[row], t1 = pT[row + 8];
                float w0 = w1row[col], w1v = w1row[col + 1];
                float c0 = pC[col],   c1 = pC[col + 1];
                float2 o0 = make_float2(tanhf(a[0] + t0 * w0 + c0),
                                        tanhf(a[1] + t0 * w1v + c1));
                float2 o1 = make_float2(tanhf(a[2] + t1 * w0 + c0),
                                        tanhf(a[3] + t1 * w1v + c1));
                *(float2*)(outp + i0) = o0;
                *(float2*)(outp + i1) = o1;
            } else if constexpr (TMODE == TM_P) {
                float2 h0 = *(const float2*)(g_h2 + i0);
                float2 h1v = *(const float2*)(g_h2 + i1);
                float2 v0 = *(const float2*)(g_V + i0);
                float2 v1 = *(const float2*)(g_V + i1);
                float2 o0 = make_float2(
                    (1.f - h0.x*h0.x) * (a[0] - 2.f*h0.x*v0.x),
                    (1.f - h0.y*h0.y) * (a[1] - 2.f*h0.y*v0.y));
                float2 o1 = make_float2(
                    (1.f - h1v.x*h1v.x) * (a[2] - 2.f*h1v.x*v1.x),
                    (1.f - h1v.y*h1v.y) * (a[3] - 2.f*h1v.y*v1.y));
                *(float2*)(outp + i0) = o0;
                *(float2*)(outp + i1) = o1;
            } else {
                *(float2*)(outp + i0) = make_float2(a[0], a[1]);
                *(float2*)(outp + i1) = make_float2(a[2], a[3]);
            }
        }
}

// ---------------- st_red: h2 = tanh(r1+b2); s_t = sum (1-h2^2)*z2*w3s ---------
__global__ void __launch_bounds__(256)
st_red(const float* __restrict__ b2) {
    __shared__ float sh[8];
    const int tid = threadIdx.x;
    const int row = blockIdx.x * 4 + (tid >> 6);
    const int j   = (tid & 63) * 8;
    const size_t idx = (size_t)row * NH + j;
    float4 ra = *(const float4*)(g_r1 + idx);
    float4 rb = *(const float4*)(g_r1 + idx + 4);
    float4 za = *(const float4*)(g_r2 + idx);
    float4 zb = *(const float4*)(g_r2 + idx + 4);
    float4 wa = *(const float4*)(g_w3s + j);
    float4 wb = *(const float4*)(g_w3s + j + 4);
    float4 ba = *(const float4*)(b2 + j);
    float4 bb = *(const float4*)(b2 + j + 4);
    float4 ha = make_float4(tanhf(ra.x + ba.x), tanhf(ra.y + ba.y),
                            tanhf(ra.z + ba.z), tanhf(ra.w + ba.w));
    float4 hb = make_float4(tanhf(rb.x + bb.x), tanhf(rb.y + bb.y),
                            tanhf(rb.z + bb.z), tanhf(rb.w + bb.w));
    *(float4*)(g_h2 + idx)     = ha;
    *(float4*)(g_h2 + idx + 4) = hb;
    float p = (1.f - ha.x*ha.x) * za.x * wa.x + (1.f - ha.y*ha.y) * za.y * wa.y
            + (1.f - ha.z*ha.z) * za.z * wa.z + (1.f - ha.w*ha.w) * za.w * wa.w
            + (1.f - hb.x*hb.x) * zb.x * wb.x + (1.f - hb.y*hb.y) * zb.y * wb.y
            + (1.f - hb.z*hb.z) * zb.z * wb.z + (1.f - hb.w*hb.w) * zb.w * wb.w;
#pragma unroll
    for (int o = 16; o; o >>= 1) p += __shfl_xor_sync(0xffffffffu, p, o);
    if ((tid & 31) == 0) sh[tid >> 5] = p;
    __syncthreads();
    if (tid < 4)
        g_st[blockIdx.x * 4 + tid] = sh[tid * 2] + sh[tid * 2 + 1];
}

// ---------------- thin SIMT GEMMs (N=64 outputs) -------------------------------
enum { M_S = 2, M_LOSS = 6 };

template<int MODE, int KDIM, int LDA, int LDB>
__global__ void __launch_bounds__(256)
gemm_k(const float* __restrict__ pB, const float* __restrict__ pC,
       const float* __restrict__ pD, float* __restrict__ pOut) {
    constexpr int BK = 32;
    __shared__ __align__(16) float Xs[BK][17];
    __shared__ __align__(16) float Bs[BK][68];
    const int tid = threadIdx.x;
    const int tx = tid & 15, ty = tid >> 4;
    const int m0 = blockIdx.y * 16;
    const float* Bg = (MODE == M_S) ? pB : g_W1T;

    float acc[4] = {0.f, 0.f, 0.f, 0.f};
    for (int k0 = 0; k0 < KDIM; k0 += BK) {
        {
            int row = tid >> 4;
            int kc  = (tid & 15) * 2;
            size_t idx = (size_t)(m0 + row) * LDA + k0 + kc;
            if constexpr (MODE == M_S) {
                float2 v = *(const float2*)(g_h2 + idx);
                Xs[kc][row] = v.x; Xs[kc + 1][row] = v.y;
            } else {
                float2 q = *(const float2*)(g_r1 + idx);
                float2 h = *(const float2*)(g_h1 + idx);
                float2 u = *(const float2*)(g_U + idx);
                float a0 = 1.f - h.x * h.x, a1v = 1.f - h.y * h.y;
                Xs[kc][row]     = a0  * q.x - 2.f * h.x * a0  * u.x;
                Xs[kc + 1][row] = a1v * q.y - 2.f * h.y * a1v * u.y;
            }
        }
        {
            int brow = tid >> 4, bnq = (tid & 15) * 4;
            *(float4*)&Bs[brow][bnq] =
                *(const float4*)(Bg + (size_t)(k0 + brow) * LDB + bnq);
            *(float4*)&Bs[brow + 16][bnq] =
                *(const float4*)(Bg + (size_t)(k0 + brow + 16) * LDB + bnq);
        }
        __syncthreads();
#pragma unroll
        for (int kk = 0; kk < BK; kk++) {
            float a = Xs[kk][ty];
            float4 b = *(const float4*)&Bs[kk][tx * 4];
            acc[0] += a * b.x; acc[1] += a * b.y;
            acc[2] += a * b.z; acc[3] += a * b.w;
        }
        __syncthreads();
    }
    const int row = m0 + ty, col = tx * 4;
    if constexpr (MODE == M_S) {
#pragma unroll
        for (int c = 0; c < 4; c++) {
            size_t idx = (size_t)row * ND + col + c;
            float sv = acc[c] + pC[col + c];
            g_s[idx] = sv;
            g_y[idx] = 2.f * sv + pD[idx];
        }
    } else {
        float stv = g_st[row], bet = pC[row];
        float ps = 0.f;
#pragma unroll
        for (int c = 0; c < 4; c++) {
            float g = acc[c] + g_s[(size_t)row * ND + col + c];
            ps += fabsf(stv - 0.5f * bet * g);
        }
#pragma unroll
        for (int o = 8; o; o >>= 1) ps += __shfl_xor_sync(0xffffffffu, ps, o);
        if (tx == 0) pOut[row] = ps * (1.f / 64.f);
    }
}

// ---------------- launch -----------------------------------------------------
#define SM64  (2 * 64 * 128 + 16384)    // 32 KB
#define SM128 (2 * 128 * 128 + 16384)   // 48 KB

extern "C" void kernel_launch(void* const* d_in, const int* in_sizes, int n_in,
                              void* d_out, int out_size) {
    const float* x    = (const float*)d_in[0];
    const float* t    = (const float*)d_in[1];
    const float* beta = (const float*)d_in[2];
    const float* W1   = (const float*)d_in[3];
    const float* b1   = (const float*)d_in[4];
    const float* W2   = (const float*)d_in[5];
    const float* b2   = (const float*)d_in[6];
    const float* W3   = (const float*)d_in[7];
    const float* b3   = (const float*)d_in[8];
    float* out = (float*)d_out;
    const float* w1t = W1 + (size_t)ND * NH;   // W1 row 64 (t-row)

    dim3 gThin(1, NB/16);          // 64 blocks
    dim3 gT128(NH/64, NB/128, 2);  // (8,8,2) = 128 blocks
    dim3 gT64 (NH/64, NB/64,  1);  // (8,16)  = 128 blocks

    prep_kernel<<<dim3(NH/16, NH/16), dim3(16,16)>>>(W1, W2, W3);
    // h1 = tanh([x,t] @ W1 + b1)                     (tensor, K=64 + rank-1)
    tmma<TM_L1, 64, 64, 64, 64><<<gT64, 256, SM64>>>(x, nullptr, b1, t, w1t);
    // h2raw = h1 @ W2 ; z2 = d1 @ W2                 (tensor dual, K=512)
    tmma<TM_H2, NH, NH, NH, 128><<<gT128, 256, SM128>>>(nullptr, nullptr, nullptr, nullptr, w1t);
    // h2 = tanh(h2raw + b2); s_t                     (fused, 256 blocks)
    st_red<<<NB/4, 256>>>(b2);
    // V = a1 @ A ; U = a2 @ A^T                      (tensor dual, K=512)
    tmma<TM_VU, NH, NH, NH, 128><<<gT128, 256, SM128>>>(nullptr, nullptr, nullptr, nullptr, w1t);
    // s = h2 @ W3 + b3 ; y = 2s + x                  (thin SIMT)
    gemm_k<M_S, NH, NH, ND><<<gThin, 256>>>(W3, b3, x, nullptr);
    // P = y @ W3^T ; wb = a2*(P - 2 h2 V)            (tensor, K=64)
    tmma<TM_P, 64, 64, 64, 64><<<gT64, 256, SM64>>>(nullptr, W3, nullptr, nullptr, w1t);
    // qw_raw = wb @ W2^T                             (tensor, K=512)
    tmma<TM_QW, NH, NH, NH, 64><<<gT64, 256, SM64>>>(nullptr, W2, nullptr, nullptr, w1t);
    // c on the fly; G = c @ W1x^T + s; loss          (thin SIMT)
    gemm_k<M_LOSS, NH, NH, ND><<<gThin, 256>>>(nullptr, beta, nullptr, out);
}

// round 8
// speedup vs baseline: 1.4503x; 1.4503x over previous
#include <cuda_runtime.h>
#include <cuda_bf16.h>
#include <math.h>
#include <stdint.h>

#define NB 1024
#define ND 64
#define NH 512

typedef __nv_bfloat16 bf16;

// ---------------- fp32 scratch ----------------
__device__ __align__(256) float g_W1T[NH*ND];   // [k,i] = W1[i,k]
__device__ __align__(256) float g_w3s[NH];
__device__ __align__(256) float g_h1 [NB*NH];
__device__ __align__(256) float g_h2 [NB*NH];
__device__ __align__(256) float g_U  [NB*NH];
__device__ __align__(256) float g_V  [NB*NH];
__device__ __align__(256) float g_r1 [NB*NH];   // qw
__device__ __align__(256) float g_r2 [NB*NH];   // z2
__device__ __align__(256) float g_s  [NB*ND];
__device__ __align__(256) float g_y  [NB*ND];
__device__ __align__(256) float g_st [NB];

// ---------------- bf16 hi/lo pre-split scratch ----------------
__device__ __align__(256) bf16 g_W1Ts_h[NH*ND], g_W1Ts_l[NH*ND]; // [n,k]=W1[k,n]
__device__ __align__(256) bf16 g_W3s_h [NH*ND], g_W3s_l [NH*ND]; // [n,j]=W3[n,j]
__device__ __align__(256) bf16 g_W2Ts_h[NH*NH], g_W2Ts_l[NH*NH]; // [n,k]=W2[k,n]
__device__ __align__(256) bf16 g_W2s_h [NH*NH], g_W2s_l [NH*NH]; // [n,k]=W2[n,k]
__device__ __align__(256) bf16 g_As_h  [NH*NH], g_As_l  [NH*NH]; // [n,k]=A[n,k]
__device__ __align__(256) bf16 g_ATs_h [NH*NH], g_ATs_l [NH*NH]; // [n,k]=A[k,n]
__device__ __align__(256) bf16 g_h1s_h [NB*NH], g_h1s_l [NB*NH];
__device__ __align__(256) bf16 g_d1s_h [NB*NH], g_d1s_l [NB*NH];
__device__ __align__(256) bf16 g_a1s_h [NB*NH], g_a1s_l [NB*NH];
__device__ __align__(256) bf16 g_a2s_h [NB*NH], g_a2s_l [NB*NH];
__device__ __align__(256) bf16 g_wbs_h [NB*NH], g_wbs_l [NB*NH];

// ---------------- helpers ------------------------------------------------
__device__ __forceinline__ uint32_t smem_u32(const void* p) {
    return (uint32_t)__cvta_generic_to_shared(p);
}
__device__ __forceinline__ void sts_v2(uint32_t addr, uint32_t a, uint32_t b) {
    asm volatile("st.shared.v2.b32 [%0], {%1,%2};" :: "r"(addr), "r"(a), "r"(b));
}
__device__ __forceinline__ void cp16(uint32_t saddr, const void* gaddr) {
    asm volatile("cp.async.cg.shared.global [%0], [%1], 16;"
                 :: "r"(saddr), "l"(gaddr));
}
__device__ __forceinline__ void cp_commit() {
    asm volatile("cp.async.commit_group;" ::: "memory");
}
template<int N> __device__ __forceinline__ void cp_wait() {
    asm volatile("cp.async.wait_group %0;" :: "n"(N) : "memory");
}
__device__ __forceinline__ void split2(float x0, float x1, uint32_t& hi, uint32_t& lo) {
    bf16 h0 = __float2bfloat16(x0), h1 = __float2bfloat16(x1);
    bf16 l0 = __float2bfloat16(x0 - __bfloat162float(h0));
    bf16 l1 = __float2bfloat16(x1 - __bfloat162float(h1));
    __nv_bfloat162 H; H.x = h0; H.y = h1;
    __nv_bfloat162 L; L.x = l0; L.y = l1;
    hi = *reinterpret_cast<uint32_t*>(&H);
    lo = *reinterpret_cast<uint32_t*>(&L);
}
__device__ __forceinline__ void splitf(float v, bf16* H, bf16* L, size_t idx) {
    bf16 h = __float2bfloat16(v);
    H[idx] = h;
    L[idx] = __float2bfloat16(v - __bfloat162float(h));
}
__device__ __forceinline__ void store_split(bf16* H, bf16* L, size_t idx,
                                            float v0, float v1) {
    uint32_t hi, lo; split2(v0, v1, hi, lo);
    *reinterpret_cast<uint32_t*>(H + idx) = hi;
    *reinterpret_cast<uint32_t*>(L + idx) = lo;
}
__device__ __forceinline__ void ldsm_x4(uint32_t* r, uint32_t addr) {
    asm volatile("ldmatrix.sync.aligned.m8n8.x4.shared.b16 {%0,%1,%2,%3}, [%4];"
                 : "=r"(r[0]), "=r"(r[1]), "=r"(r[2]), "=r"(r[3]) : "r"(addr));
}
__device__ __forceinline__ void ldsm_x2(uint32_t* r, uint32_t addr) {
    asm volatile("ldmatrix.sync.aligned.m8n8.x2.shared.b16 {%0,%1}, [%2];"
                 : "=r"(r[0]), "=r"(r[1]) : "r"(addr));
}
__device__ __forceinline__ void mma16816(float* c, const uint32_t* a, const uint32_t* b) {
    asm volatile(
        "mma.sync.aligned.m16n8k16.row.col.f32.bf16.bf16.f32 "
        "{%0,%1,%2,%3}, {%4,%5,%6,%7}, {%8,%9}, {%0,%1,%2,%3};"
        : "+f"(c[0]), "+f"(c[1]), "+f"(c[2]), "+f"(c[3])
        : "r"(a[0]), "r"(a[1]), "r"(a[2]), "r"(a[3]), "r"(b[0]), "r"(b[1]));
}
__device__ __forceinline__ uint32_t sw128(uint32_t byte) {
    return byte ^ ((byte >> 3) & 0x70);
}

// ---------------- prep: weights + derived matrices, pre-split ----------------
__global__ void prep_kernel(const float* __restrict__ W1,
                            const float* __restrict__ W2,
                            const float* __restrict__ W3) {
    __shared__ float w2ts[16][17];
    const int tx = threadIdx.x, ty = threadIdx.y;
    const int r = blockIdx.y * 16 + ty;
    const int c = blockIdx.x * 16 + tx;
    // coalesced staged transpose: w2ts[i][j] = W2[(cblk+i)*NH + rblk+j]
    w2ts[ty][tx] = W2[(size_t)(blockIdx.x * 16 + ty) * NH + blockIdx.y * 16 + tx];
    __syncthreads();
    float w2rc = W2[(size_t)r * NH + c];
    float w2cr = w2ts[tx][ty];
    float d1 = 0.f, d2 = 0.f;
#pragma unroll
    for (int i = 0; i < ND; i++) {
        d1 += W3[c * ND + i] * W1[i * NH + r];
        d2 += W3[r * ND + i] * W1[i * NH + c];
    }
    const size_t idx = (size_t)r * NH + c;
    splitf(w2rc,      g_W2s_h,  g_W2s_l,  idx);
    splitf(w2cr,      g_W2Ts_h, g_W2Ts_l, idx);
    splitf(w2rc * d1, g_As_h,   g_As_l,   idx);   // A[r,c]
    splitf(w2cr * d2, g_ATs_h,  g_ATs_l,  idx);   // A[c,r]
    if (c < ND) {
        float w1v = W1[c * NH + r];
        g_W1T[r * ND + c] = w1v;
        splitf(w1v,          g_W1Ts_h, g_W1Ts_l, (size_t)r * ND + c);
        splitf(W3[r*ND + c], g_W3s_h,  g_W3s_l,  (size_t)r * ND + c);
    }
    if (blockIdx.y == 0 && ty == 0) {
        float s1 = 0.f;
#pragma unroll
        for (int j = 0; j < ND; j++) s1 += W3[c * ND + j];
        g_w3s[c] = s1;
    }
}

// ---------------- tensor GEMMs -----------------------------------------------
enum { TM_L1 = 0, TM_H2 = 1, TM_VU = 2, TM_P = 3, TM_QW = 4 };

template<int TMODE, int BM>
__global__ void __launch_bounds__(256, 1)
tmma(const float* __restrict__ pX, const float* __restrict__ pC,
     const float* __restrict__ pT, const float* __restrict__ w1row) {
    extern __shared__ __align__(1024) char tsm[];
    const uint32_t sb = smem_u32(tsm);
    constexpr bool PIPE = (TMODE == TM_H2 || TMODE == TM_VU || TMODE == TM_QW);
    constexpr int NCHUNK = PIPE ? 8 : 1;
    constexpr uint32_t XSZ = BM * 128;
    constexpr uint32_t OXH = 0, OXL = XSZ, OBH = 2 * XSZ, OBL = 2 * XSZ + 8192;
    constexpr uint32_t STAGE = 2 * XSZ + 16384;
    constexpr int NT = (BM == 128) ? 4 : 2;
    constexpr int LDBW = (TMODE == TM_L1 || TMODE == TM_P) ? ND : NH;

    const int tid = threadIdx.x, lane = tid & 31, wid = tid >> 5;
    const int zm = blockIdx.z;
    const int n0 = blockIdx.x * 64, m0 = blockIdx.y * BM;
    const int wm = (BM == 128 ? (wid & 3) : (wid & 1)) * 32;
    const int wn = (BM == 128 ? (wid >> 2) * 32 : (wid >> 1) * 16);

    const bf16 *Xh = nullptr, *Xl = nullptr;
    if constexpr (TMODE == TM_H2) { Xh = zm ? g_d1s_h : g_h1s_h; Xl = zm ? g_d1s_l : g_h1s_l; }
    else if constexpr (TMODE == TM_VU) { Xh = zm ? g_a2s_h : g_a1s_h; Xl = zm ? g_a2s_l : g_a1s_l; }
    else if constexpr (TMODE == TM_QW) { Xh = g_wbs_h; Xl = g_wbs_l; }
    const bf16 *Bh, *Bl;
    if constexpr (TMODE == TM_L1)      { Bh = g_W1Ts_h; Bl = g_W1Ts_l; }
    else if constexpr (TMODE == TM_H2) { Bh = g_W2Ts_h; Bl = g_W2Ts_l; }
    else if constexpr (TMODE == TM_VU) { Bh = zm ? g_As_h : g_ATs_h; Bl = zm ? g_As_l : g_ATs_l; }
    else if constexpr (TMODE == TM_P)  { Bh = g_W3s_h; Bl = g_W3s_l; }
    else                               { Bh = g_W2s_h; Bl = g_W2s_l; }

    const int xrow = (BM == 128) ? (tid >> 1) : (tid >> 2);
    const int xcb  = (BM == 128) ? ((tid & 1) * 32) : ((tid & 3) * 16);
    const int brow = tid >> 2, bcb = (tid & 3) * 16;

    auto cpX = [&](int ch, uint32_t st) {
        constexpr int NI = (BM == 128) ? 4 : 2;
        size_t base = (size_t)(m0 + xrow) * NH + ch * 64 + xcb;
#pragma unroll
        for (int i = 0; i < NI; i++) {
            int col = xcb + i * 8;
            uint32_t sw = sw128((uint32_t)xrow * 128 + col * 2);
            cp16(st + OXH + sw, Xh + base + i * 8);
            cp16(st + OXL + sw, Xl + base + i * 8);
        }
    };
    auto cpB = [&](int ch, uint32_t st) {
        size_t base = (size_t)(n0 + brow) * LDBW + (PIPE ? ch * 64 : 0) + bcb;
#pragma unroll
        for (int i = 0; i < 2; i++) {
            int col = bcb + i * 8;
            uint32_t sw = sw128((uint32_t)brow * 128 + col * 2);
            cp16(st + OBH + sw, Bh + base + i * 8);
            cp16(st + OBL + sw, Bl + base + i * 8);
        }
    };
    auto stXinline = [&](uint32_t st) {   // L1 / P only (BM=64, K=64 fp32)
        const int row = tid >> 2, cb = (tid & 3) * 16;
        const float* src = (TMODE == TM_L1) ? pX : g_y;
        const float* xr = src + (size_t)(m0 + row) * 64 + cb;
#pragma unroll
        for (int i = 0; i < 4; i++) {
            float4 v = *(const float4*)(xr + i * 4);
            uint32_t h01, l01, h23, l23;
            split2(v.x, v.y, h01, l01);
            split2(v.z, v.w, h23, l23);
            uint32_t sw = sw128((uint32_t)row * 128 + (cb + i * 4) * 2);
            sts_v2(st + OXH + sw, h01, h23);
            sts_v2(st + OXL + sw, l01, l23);
        }
    };

    float acc[2][NT][4];
#pragma unroll
    for (int mt = 0; mt < 2; mt++)
#pragma unroll
        for (int nt = 0; nt < NT; nt++)
#pragma unroll
            for (int i = 0; i < 4; i++) acc[mt][nt][i] = 0.f;

    if constexpr (PIPE) { cpX(0, sb); cpB(0, sb); cp_commit(); }
    else                { cpB(0, sb); cp_commit(); stXinline(sb); }

    for (int ch = 0; ch < NCHUNK; ch++) {
        const uint32_t st = sb + (uint32_t)(ch & 1) * STAGE;
        if constexpr (PIPE) {
            if (ch + 1 < NCHUNK) {
                const uint32_t st2 = sb + (uint32_t)((ch + 1) & 1) * STAGE;
                cpX(ch + 1, st2); cpB(ch + 1, st2); cp_commit();
                cp_wait<1>();
            } else cp_wait<0>();
        } else cp_wait<0>();
        __syncthreads();

#pragma unroll
        for (int ks = 0; ks < 4; ks++) {
            uint32_t aH[2][4], aL[2][4];
#pragma unroll
            for (int mt = 0; mt < 2; mt++) {
                uint32_t byte = (uint32_t)(wm + mt * 16 + (lane & 15)) * 128
                              + ks * 32 + (lane >> 4) * 16;
                uint32_t sw = sw128(byte);
                ldsm_x4(aH[mt], st + OXH + sw);
                ldsm_x4(aL[mt], st + OXL + sw);
            }
            uint32_t bH[NT][2], bL[NT][2];
#pragma unroll
            for (int nt = 0; nt < NT; nt++) {
                uint32_t byte = (uint32_t)(wn + nt * 8 + (lane & 7)) * 128
                              + ks * 32 + ((lane >> 3) & 1) * 16;
                uint32_t sw = sw128(byte);
                ldsm_x2(bH[nt], st + OBH + sw);
                ldsm_x2(bL[nt], st + OBL + sw);
            }
#pragma unroll
            for (int mt = 0; mt < 2; mt++)
#pragma unroll
                for (int nt = 0; nt < NT; nt++) {
                    mma16816(acc[mt][nt], aH[mt], bH[nt]);
                    mma16816(acc[mt][nt], aH[mt], bL[nt]);
                    mma16816(acc[mt][nt], aL[mt], bH[nt]);
                }
        }
        __syncthreads();
    }

    // ---- epilogues ----
#pragma unroll
    for (int mt = 0; mt < 2; mt++)
#pragma unroll
        for (int nt = 0; nt < NT; nt++) {
            const int r0  = m0 + wm + mt * 16 + (lane >> 2);
            const int col = n0 + wn + nt * 8 + (lane & 3) * 2;
            const float* a = acc[mt][nt];
#pragma unroll
            for (int half = 0; half < 2; half++) {
                const int row = r0 + half * 8;
                const float e0 = a[half * 2], e1 = a[half * 2 + 1];
                const size_t idx = (size_t)row * NH + col;
                if constexpr (TMODE == TM_L1) {
                    float tv = pT[row];
                    float h0 = tanhf(e0 + tv * w1row[col]     + pC[col]);
                    float h1 = tanhf(e1 + tv * w1row[col + 1] + pC[col + 1]);
                    *(float2*)(g_h1 + idx) = make_float2(h0, h1);
                    store_split(g_h1s_h, g_h1s_l, idx, h0, h1);
                    float a0 = 1.f - h0 * h0, a1v = 1.f - h1 * h1;
                    store_split(g_a1s_h, g_a1s_l, idx, a0, a1v);
                    store_split(g_d1s_h, g_d1s_l, idx,
                                a0 * w1row[col], a1v * w1row[col + 1]);
                } else if constexpr (TMODE == TM_H2) {
                    if (zm == 0) {
                        float h0 = tanhf(e0 + pC[col]);
                        float h1 = tanhf(e1 + pC[col + 1]);
                        *(float2*)(g_h2 + idx) = make_float2(h0, h1);
                        store_split(g_a2s_h, g_a2s_l, idx,
                                    1.f - h0 * h0, 1.f - h1 * h1);
                    } else {
                        *(float2*)(g_r2 + idx) = make_float2(e0, e1);
                    }
                } else if constexpr (TMODE == TM_VU) {
                    float* o = zm ? g_U : g_V;
                    *(float2*)(o + idx) = make_float2(e0, e1);
                } else if constexpr (TMODE == TM_P) {
                    float2 h = *(const float2*)(g_h2 + idx);
                    float2 v = *(const float2*)(g_V + idx);
                    float w0 = (1.f - h.x * h.x) * (e0 - 2.f * h.x * v.x);
                    float w1 = (1.f - h.y * h.y) * (e1 - 2.f * h.y * v.y);
                    store_split(g_wbs_h, g_wbs_l, idx, w0, w1);
                } else {  // TM_QW
                    *(float2*)(g_r1 + idx) = make_float2(e0, e1);
                }
            }
        }
}

// ---------------- st_red: s_t = sum (1-h2^2)*z2*w3s ---------------------------
__global__ void __launch_bounds__(256)
st_red() {
    __shared__ float sh[8];
    const int tid = threadIdx.x;
    const int row = blockIdx.x * 4 + (tid >> 6);
    const int j   = (tid & 63) * 8;
    const size_t idx = (size_t)row * NH + j;
    float4 ha = *(const float4*)(g_h2 + idx);
    float4 hb = *(const float4*)(g_h2 + idx + 4);
    float4 za = *(const float4*)(g_r2 + idx);
    float4 zb = *(const float4*)(g_r2 + idx + 4);
    float4 wa = *(const float4*)(g_w3s + j);
    float4 wb = *(const float4*)(g_w3s + j + 4);
    float p = (1.f - ha.x*ha.x) * za.x * wa.x + (1.f - ha.y*ha.y) * za.y * wa.y
            + (1.f - ha.z*ha.z) * za.z * wa.z + (1.f - ha.w*ha.w) * za.w * wa.w
            + (1.f - hb.x*hb.x) * zb.x * wb.x + (1.f - hb.y*hb.y) * zb.y * wb.y
            + (1.f - hb.z*hb.z) * zb.z * wb.z + (1.f - hb.w*hb.w) * zb.w * wb.w;
#pragma unroll
    for (int o = 16; o; o >>= 1) p += __shfl_xor_sync(0xffffffffu, p, o);
    if ((tid & 31) == 0) sh[tid >> 5] = p;
    __syncthreads();
    if (tid < 4)
        g_st[blockIdx.x * 4 + tid] = sh[tid * 2] + sh[tid * 2 + 1];
}

// ---------------- thin SIMT GEMMs (N=64 outputs) ------------------------------
enum { M_S = 2, M_LOSS = 6 };

template<int MODE, int KDIM, int LDA, int LDB>
__global__ void __launch_bounds__(256)
gemm_k(const float* __restrict__ pB, const float* __restrict__ pC,
       const float* __restrict__ pD, float* __restrict__ pOut) {
    constexpr int BK = 32;
    __shared__ __align__(16) float Xs[BK][17];
    __shared__ __align__(16) float Bs[BK][68];
    const int tid = threadIdx.x;
    const int tx = tid & 15, ty = tid >> 4;
    const int m0 = blockIdx.y * 16;
    const float* Bg = (MODE == M_S) ? pB : g_W1T;

    float acc[4] = {0.f, 0.f, 0.f, 0.f};
    for (int k0 = 0; k0 < KDIM; k0 += BK) {
        {
            int row = tid >> 4;
            int kc  = (tid & 15) * 2;
            size_t idx = (size_t)(m0 + row) * LDA + k0 + kc;
            if constexpr (MODE == M_S) {
                float2 v = *(const float2*)(g_h2 + idx);
                Xs[kc][row] = v.x; Xs[kc + 1][row] = v.y;
            } else {
                float2 q = *(const float2*)(g_r1 + idx);
                float2 h = *(const float2*)(g_h1 + idx);
                float2 u = *(const float2*)(g_U + idx);
                float a0 = 1.f - h.x * h.x, a1v = 1.f - h.y * h.y;
                Xs[kc][row]     = a0  * q.x - 2.f * h.x * a0  * u.x;
                Xs[kc + 1][row] = a1v * q.y - 2.f * h.y * a1v * u.y;
            }
        }
        {
            int brow = tid >> 4, bnq = (tid & 15) * 4;
            *(float4*)&Bs[brow][bnq] =
                *(const float4*)(Bg + (size_t)(k0 + brow) * LDB + bnq);
            *(float4*)&Bs[brow + 16][bnq] =
                *(const float4*)(Bg + (size_t)(k0 + brow + 16) * LDB + bnq);
        }
        __syncthreads();
#pragma unroll
        for (int kk = 0; kk < BK; kk++) {
            float a = Xs[kk][ty];
            float4 b = *(const float4*)&Bs[kk][tx * 4];
            acc[0] += a * b.x; acc[1] += a * b.y;
            acc[2] += a * b.z; acc[3] += a * b.w;
        }
        __syncthreads();
    }
    const int row = m0 + ty, col = tx * 4;
    if constexpr (MODE == M_S) {
#pragma unroll
        for (int c = 0; c < 4; c++) {
            size_t idx = (size_t)row * ND + col + c;
            float sv = acc[c] + pC[col + c];
            g_s[idx] = sv;
            g_y[idx] = 2.f * sv + pD[idx];
        }
    } else {
        float stv = g_st[row], bet = pC[row];
        float ps = 0.f;
#pragma unroll
        for (int c = 0; c < 4; c++) {
            float g = acc[c] + g_s[(size_t)row * ND + col + c];
            ps += fabsf(stv - 0.5f * bet * g);
        }
#pragma unroll
        for (int o = 8; o; o >>= 1) ps += __shfl_xor_sync(0xffffffffu, ps, o);
        if (tx == 0) pOut[row] = ps * (1.f / 64.f);
    }
}

// ---------------- launch -----------------------------------------------------
#define SM_P128 (2 * (2 * 128 * 128 + 16384))   // 98304
#define SM_P64  (2 * (2 * 64 * 128 + 16384))    // 65536
#define SM_S64  (2 * 64 * 128 + 16384)          // 32768

extern "C" void kernel_launch(void* const* d_in, const int* in_sizes, int n_in,
                              void* d_out, int out_size) {
    const float* x    = (const float*)d_in[0];
    const float* t    = (const float*)d_in[1];
    const float* beta = (const float*)d_in[2];
    const float* W1   = (const float*)d_in[3];
    const float* b1   = (const float*)d_in[4];
    const float* W2   = (const float*)d_in[5];
    const float* b2   = (const float*)d_in[6];
    const float* W3   = (const float*)d_in[7];
    const float* b3   = (const float*)d_in[8];
    float* out = (float*)d_out;
    const float* w1t = W1 + (size_t)ND * NH;   // W1 t-row

    cudaFuncSetAttribute(tmma<TM_L1, 64>,  cudaFuncAttributeMaxDynamicSharedMemorySize, SM_S64);
    cudaFuncSetAttribute(tmma<TM_H2, 128>, cudaFuncAttributeMaxDynamicSharedMemorySize, SM_P128);
    cudaFuncSetAttribute(tmma<TM_VU, 128>, cudaFuncAttributeMaxDynamicSharedMemorySize, SM_P128);
    cudaFuncSetAttribute(tmma<TM_P, 64>,   cudaFuncAttributeMaxDynamicSharedMemorySize, SM_S64);
    cudaFuncSetAttribute(tmma<TM_QW, 64>,  cudaFuncAttributeMaxDynamicSharedMemorySize, SM_P64);

    dim3 gThin(1, NB/16);          // 64 blocks
    dim3 gT128(NH/64, NB/128, 2);  // 128 blocks
    dim3 gT64 (NH/64, NB/64,  1);  // 128 blocks

    prep_kernel<<<dim3(NH/16, NH/16), dim3(16,16)>>>(W1, W2, W3);
    // h1 = tanh([x,t]@W1 + b1); writes h1, h1s, a1s, d1s
    tmma<TM_L1, 64><<<gT64, 256, SM_S64>>>(x, b1, t, w1t);
    // z0: h2 = tanh(h1@W2 + b2) (+a2s); z1: z2 = d1@W2
    tmma<TM_H2, 128><<<gT128, 256, SM_P128>>>(nullptr, b2, nullptr, nullptr);
    // s_t
    st_red<<<NB/4, 256>>>();
    // z0: V = a1@A; z1: U = a2@A^T
    tmma<TM_VU, 128><<<gT128, 256, SM_P128>>>(nullptr, nullptr, nullptr, nullptr);
    // s = h2@W3 + b3; y = 2s + x
    gemm_k<M_S, NH, NH, ND><<<gThin, 256>>>(W3, b3, x, nullptr);
    // P = y@W3^T; wb = a2*(P - 2 h2 V) -> wbs
    tmma<TM_P, 64><<<gT64, 256, SM_S64>>>(nullptr, nullptr, nullptr, nullptr);
    // qw = wb@W2^T
    tmma<TM_QW, 64><<<gT64, 256, SM_P64>>>(nullptr, nullptr, nullptr, nullptr);
    // c on the fly; G = c@W1x^T + s; loss
    gemm_k<M_LOSS, NH, NH, ND><<<gThin, 256>>>(nullptr, beta, nullptr, out);
}